// round 4
// baseline (speedup 1.0000x reference)
#include <cuda_runtime.h>
#include <cuda_bf16.h>
#include <math.h>
#include <stdint.h>

#define BB 16
#define SS 2048
#define DD 512
typedef __nv_bfloat16 bf16;

// ---------------------------------------------------------------------------
// Scratch (device globals — no allocation allowed)
// ---------------------------------------------------------------------------
__device__ float g_Wkp[DD * DD];
__device__ float g_Wvp[DD * DD];
__device__ float g_bkp[DD];
__device__ float g_bvp[DD];

__device__ bf16 g_Wq_hi[DD * DD],  g_Wq_lo[DD * DD];
__device__ bf16 g_Wkp_hi[DD * DD], g_Wkp_lo[DD * DD];
__device__ bf16 g_Wvp_hi[DD * DD], g_Wvp_lo[DD * DD];
__device__ bf16 g_Wo_hi[DD * DD],  g_Wo_lo[DD * DD];
__device__ bf16 g_q_hi[(size_t)BB * SS * DD],  g_q_lo[(size_t)BB * SS * DD];
__device__ bf16 g_kp_hi[(size_t)BB * SS * DD], g_kp_lo[(size_t)BB * SS * DD];
__device__ bf16 g_vpT_hi[(size_t)BB * SS * DD], g_vpT_lo[(size_t)BB * SS * DD];
__device__ bf16 g_attn_hi[(size_t)BB * SS * SS], g_attn_lo[(size_t)BB * SS * SS];
__device__ bf16 g_op_hi[(size_t)BB * SS * DD],  g_op_lo[(size_t)BB * SS * DD];

// ---------------------------------------------------------------------------
// helpers (portable sm_80+ feature set only: cp.async / ldmatrix / mma.sync)
// ---------------------------------------------------------------------------
__device__ __forceinline__ uint32_t smem_u32(const void* p) {
    uint32_t a;
    asm("{ .reg .u64 t; cvta.to.shared.u64 t, %1; cvt.u32.u64 %0, t; }"
        : "=r"(a) : "l"(p));
    return a;
}
__device__ __forceinline__ void cp_async16(uint32_t dst, const void* src) {
    asm volatile("cp.async.cg.shared.global [%0], [%1], 16;"
                 :: "r"(dst), "l"(src) : "memory");
}
__device__ __forceinline__ void cp_commit() {
    asm volatile("cp.async.commit_group;" ::: "memory");
}
__device__ __forceinline__ void cp_wait1() {
    asm volatile("cp.async.wait_group 1;" ::: "memory");
}
__device__ __forceinline__ void cp_wait0() {
    asm volatile("cp.async.wait_group 0;" ::: "memory");
}
__device__ __forceinline__ void ldsm4(uint32_t r[4], uint32_t addr) {
    asm volatile("ldmatrix.sync.aligned.m8n8.x4.shared.b16 {%0,%1,%2,%3}, [%4];"
                 : "=r"(r[0]), "=r"(r[1]), "=r"(r[2]), "=r"(r[3]) : "r"(addr));
}
__device__ __forceinline__ void mma16816(float c[4], const uint32_t a[4],
                                         uint32_t b0, uint32_t b1) {
    asm volatile(
        "mma.sync.aligned.m16n8k16.row.col.f32.bf16.bf16.f32 "
        "{%0,%1,%2,%3}, {%4,%5,%6,%7}, {%8,%9}, {%0,%1,%2,%3};"
        : "+f"(c[0]), "+f"(c[1]), "+f"(c[2]), "+f"(c[3])
        : "r"(a[0]), "r"(a[1]), "r"(a[2]), "r"(a[3]), "r"(b0), "r"(b1));
}
// 8 fp32 -> 8 hi bf16 + 8 lo bf16 (packed as uint4 each)
__device__ __forceinline__ void split8(const float4 x, const float4 y,
                                       uint4& hi, uint4& lo) {
    float f[8] = {x.x, x.y, x.z, x.w, y.x, y.y, y.z, y.w};
    uint32_t h[4], l[4];
#pragma unroll
    for (int i = 0; i < 4; i++) {
        __nv_bfloat162 hh = __floats2bfloat162_rn(f[2 * i], f[2 * i + 1]);
        h[i] = *reinterpret_cast<uint32_t*>(&hh);
        float r0 = f[2 * i]     - __bfloat162float(hh.x);
        float r1 = f[2 * i + 1] - __bfloat162float(hh.y);
        __nv_bfloat162 ll = __floats2bfloat162_rn(r0, r1);
        l[i] = *reinterpret_cast<uint32_t*>(&ll);
    }
    hi = make_uint4(h[0], h[1], h[2], h[3]);
    lo = make_uint4(l[0], l[1], l[2], l[3]);
}

// shared compute body: 32-K chunk, 3 passes (AhBh, AhBl, AlBh)
__device__ __forceinline__ void compute_chunk(
    uint32_t ah, uint32_t al, uint32_t bhb, uint32_t blb,
    const uint32_t aoff[4][2], const uint32_t boff[2][2], float c[4][4][4])
{
#pragma unroll
    for (int ks = 0; ks < 2; ks++) {
        uint32_t a[4][4], bh[2][4], bl[2][4];
#pragma unroll
        for (int i = 0; i < 4; i++) ldsm4(a[i], ah + aoff[i][ks]);
#pragma unroll
        for (int j = 0; j < 2; j++) ldsm4(bh[j], bhb + boff[j][ks]);
#pragma unroll
        for (int j = 0; j < 2; j++) ldsm4(bl[j], blb + boff[j][ks]);
#pragma unroll
        for (int i = 0; i < 4; i++)
#pragma unroll
            for (int j = 0; j < 4; j++) {
                mma16816(c[i][j], a[i], bh[j >> 1][(j & 1) * 2], bh[j >> 1][(j & 1) * 2 + 1]);
                mma16816(c[i][j], a[i], bl[j >> 1][(j & 1) * 2], bl[j >> 1][(j & 1) * 2 + 1]);
            }
#pragma unroll
        for (int i = 0; i < 4; i++) ldsm4(a[i], al + aoff[i][ks]);
#pragma unroll
        for (int i = 0; i < 4; i++)
#pragma unroll
            for (int j = 0; j < 4; j++)
                mma16816(c[i][j], a[i], bh[j >> 1][(j & 1) * 2], bh[j >> 1][(j & 1) * 2 + 1]);
    }
}

#define TG_THREADS 256
#define TG_STAGE   32768
#define TG_SMEM    (128 * 136 * 4)     // 69632 (also covers 2x32KB stages)

// ---------------------------------------------------------------------------
// Pair-input GEMM (A,B hi/lo bf16): C = alpha*A@B^T (+bias); outputs fp32
// and/or hi/lo pair. (unchanged from round 3 — known good)
// ---------------------------------------------------------------------------
__global__ __launch_bounds__(TG_THREADS)
void tgemm_kernel(const bf16* __restrict__ Ahi, const bf16* __restrict__ Alo,
                  const bf16* __restrict__ Bhi, const bf16* __restrict__ Blo,
                  float* outF, bf16* outHi, bf16* outLo,
                  const float* __restrict__ bias,
                  int M, int N, int K, float alpha,
                  long long sA, long long sB, long long sC)
{
    extern __shared__ char smem[];
    const uint32_t sb = smem_u32(smem);
    const int tid  = threadIdx.x;
    const int lane = tid & 31;
    const int wid  = tid >> 5;
    const int m0   = (wid & 1) * 64;
    const int n0   = (wid >> 1) * 32;

    const long long bz = blockIdx.z;
    Ahi += bz * sA; Alo += bz * sA;
    Bhi += bz * sB; Blo += bz * sB;
    if (outF)  outF  += bz * sC;
    if (outHi) { outHi += bz * sC; outLo += bz * sC; }

    const int rowBase = blockIdx.y * 128;
    const int colBase = blockIdx.x * 128;

    int ldRow[2], ldK16[2];
    uint32_t ldOff[2];
#pragma unroll
    for (int i = 0; i < 2; i++) {
        int chunk = tid + i * 256;
        ldRow[i] = chunk >> 2;
        ldK16[i] = chunk & 3;
        ldOff[i] = (uint32_t)(ldRow[i] * 64 +
                   ((ldK16[i] ^ ((ldRow[i] >> 1) & 3)) * 16));
    }

    uint32_t aoff[4][2], boff[2][2];
#pragma unroll
    for (int i = 0; i < 4; i++)
#pragma unroll
        for (int ks = 0; ks < 2; ks++) {
            int r = m0 + i * 16 + (lane & 7) + ((lane >> 3) & 1) * 8;
            int ch = ks * 2 + (lane >> 4);
            aoff[i][ks] = (uint32_t)(r * 64 + ((ch ^ ((r >> 1) & 3)) * 16));
        }
#pragma unroll
    for (int j = 0; j < 2; j++)
#pragma unroll
        for (int ks = 0; ks < 2; ks++) {
            int r = n0 + j * 16 + (lane & 7) + ((lane >> 4) & 1) * 8;
            int ch = ks * 2 + ((lane >> 3) & 1);
            boff[j][ks] = (uint32_t)(r * 64 + ((ch ^ ((r >> 1) & 3)) * 16));
        }

    float c[4][4][4];
#pragma unroll
    for (int i = 0; i < 4; i++)
#pragma unroll
        for (int j = 0; j < 4; j++)
#pragma unroll
            for (int e = 0; e < 4; e++) c[i][j][e] = 0.0f;

    const int nc = K >> 5;

    auto load_stage = [&](int cidx) {
        const uint32_t dst = sb + (uint32_t)(cidx & 1) * TG_STAGE;
        const long long kb = (long long)cidx * 32;
#pragma unroll
        for (int i = 0; i < 2; i++) {
            const long long ea = (long long)(rowBase + ldRow[i]) * K + kb + ldK16[i] * 8;
            const long long eb = (long long)(colBase + ldRow[i]) * K + kb + ldK16[i] * 8;
            cp_async16(dst +         ldOff[i], Ahi + ea);
            cp_async16(dst +  8192 + ldOff[i], Alo + ea);
            cp_async16(dst + 16384 + ldOff[i], Bhi + eb);
            cp_async16(dst + 24576 + ldOff[i], Blo + eb);
        }
        cp_commit();
    };

    load_stage(0);

    for (int cidx = 0; cidx < nc; cidx++) {
        if (cidx + 1 < nc) { load_stage(cidx + 1); cp_wait1(); }
        else               { cp_wait0(); }
        __syncthreads();
        const uint32_t st = sb + (uint32_t)(cidx & 1) * TG_STAGE;
        compute_chunk(st, st + 8192, st + 16384, st + 24576, aoff, boff, c);
        __syncthreads();
    }

    // epilogue
    float* sf = (float*)smem;
#pragma unroll
    for (int i = 0; i < 4; i++) {
        const int r = m0 + i * 16 + (lane >> 2);
#pragma unroll
        for (int j = 0; j < 4; j++) {
            const int cc = n0 + j * 8 + (lane & 3) * 2;
            sf[r * 136 + cc]           = c[i][j][0];
            sf[r * 136 + cc + 1]       = c[i][j][1];
            sf[(r + 8) * 136 + cc]     = c[i][j][2];
            sf[(r + 8) * 136 + cc + 1] = c[i][j][3];
        }
    }
    __syncthreads();
#pragma unroll 4
    for (int e = tid; e < 128 * 128; e += TG_THREADS) {
        const int r = e >> 7, cc = e & 127;
        float v = sf[r * 136 + cc] * alpha;
        const int gc = colBase + cc;
        if (bias) v += bias[gc];
        const long long gi = (long long)(rowBase + r) * N + gc;
        if (outF) outF[gi] = v;
        if (outHi) {
            bf16 h = __float2bfloat16_rn(v);
            outHi[gi] = h;
            outLo[gi] = __float2bfloat16_rn(v - __bfloat162float(h));
        }
    }
}

// ---------------------------------------------------------------------------
// fp32-A GEMM (projections): A fp32 split in-kernel; B pre-split hi/lo bf16.
// C = A@B^T + bias -> hi/lo pair output, optionally transposed (vpT layout).
// ---------------------------------------------------------------------------
__global__ __launch_bounds__(TG_THREADS)
void tgemm_f32a_kernel(const float* __restrict__ A,
                       const bf16* __restrict__ Bhi, const bf16* __restrict__ Blo,
                       bf16* __restrict__ outHi, bf16* __restrict__ outLo,
                       const float* __restrict__ bias,
                       int M, int N, int K, int transOut)
{
    extern __shared__ char smem[];
    const uint32_t sb = smem_u32(smem);
    const int tid  = threadIdx.x;
    const int lane = tid & 31;
    const int wid  = tid >> 5;
    const int m0   = (wid & 1) * 64;
    const int n0   = (wid >> 1) * 32;

    const int rowBase = blockIdx.y * 128;
    const int colBase = blockIdx.x * 128;

    // A-load geometry: 2 units of (row, 8 floats)
    int aRow[2], aC8[2];
    uint32_t aSw[2];
#pragma unroll
    for (int i = 0; i < 2; i++) {
        int u = tid + i * 256;
        aRow[i] = u >> 2;
        aC8[i]  = u & 3;
        aSw[i]  = (uint32_t)(aRow[i] * 64 + ((aC8[i] ^ ((aRow[i] >> 1) & 3)) * 16));
    }
    // B cp.async geometry
    int ldRow[2], ldK16[2];
    uint32_t ldOff[2];
#pragma unroll
    for (int i = 0; i < 2; i++) {
        int chunk = tid + i * 256;
        ldRow[i] = chunk >> 2;
        ldK16[i] = chunk & 3;
        ldOff[i] = (uint32_t)(ldRow[i] * 64 +
                   ((ldK16[i] ^ ((ldRow[i] >> 1) & 3)) * 16));
    }

    uint32_t aoff[4][2], boff[2][2];
#pragma unroll
    for (int i = 0; i < 4; i++)
#pragma unroll
        for (int ks = 0; ks < 2; ks++) {
            int r = m0 + i * 16 + (lane & 7) + ((lane >> 3) & 1) * 8;
            int ch = ks * 2 + (lane >> 4);
            aoff[i][ks] = (uint32_t)(r * 64 + ((ch ^ ((r >> 1) & 3)) * 16));
        }
#pragma unroll
    for (int j = 0; j < 2; j++)
#pragma unroll
        for (int ks = 0; ks < 2; ks++) {
            int r = n0 + j * 16 + (lane & 7) + ((lane >> 4) & 1) * 8;
            int ch = ks * 2 + ((lane >> 3) & 1);
            boff[j][ks] = (uint32_t)(r * 64 + ((ch ^ ((r >> 1) & 3)) * 16));
        }

    float c[4][4][4];
#pragma unroll
    for (int i = 0; i < 4; i++)
#pragma unroll
        for (int j = 0; j < 4; j++)
#pragma unroll
            for (int e = 0; e < 4; e++) c[i][j][e] = 0.0f;

    const int nc = K >> 5;

    auto issueB = [&](int cidx) {
        const uint32_t dst = sb + 32768u + (uint32_t)(cidx & 1) * 16384u;
        const long long kb = (long long)cidx * 32;
#pragma unroll
        for (int i = 0; i < 2; i++) {
            const long long eb = (long long)(colBase + ldRow[i]) * K + kb + ldK16[i] * 8;
            cp_async16(dst +        ldOff[i], Bhi + eb);
            cp_async16(dst + 8192 + ldOff[i], Blo + eb);
        }
        cp_commit();
    };

    // prologue: A chunk 0 -> regs, B chunk 0 async
    float4 ar[2][2];
#pragma unroll
    for (int i = 0; i < 2; i++) {
        const float* p = A + (long long)(rowBase + aRow[i]) * K + aC8[i] * 8;
        ar[i][0] = *(const float4*)(p);
        ar[i][1] = *(const float4*)(p + 4);
    }
    issueB(0);

    for (int cidx = 0; cidx < nc; cidx++) {
        // STS A(cidx) hi/lo
        {
            char* base = smem + (cidx & 1) * 16384;
#pragma unroll
            for (int i = 0; i < 2; i++) {
                uint4 hi, lo;
                split8(ar[i][0], ar[i][1], hi, lo);
                *(uint4*)(base +        aSw[i]) = hi;
                *(uint4*)(base + 8192 + aSw[i]) = lo;
            }
        }
        if (cidx + 1 < nc) { issueB(cidx + 1); cp_wait1(); }
        else               { cp_wait0(); }
        __syncthreads();
        // prefetch next A chunk into regs
        if (cidx + 1 < nc) {
            const long long kb = (long long)(cidx + 1) * 32;
#pragma unroll
            for (int i = 0; i < 2; i++) {
                const float* p = A + (long long)(rowBase + aRow[i]) * K + kb + aC8[i] * 8;
                ar[i][0] = *(const float4*)(p);
                ar[i][1] = *(const float4*)(p + 4);
            }
        }
        const uint32_t stA = sb + (uint32_t)(cidx & 1) * 16384u;
        const uint32_t stB = sb + 32768u + (uint32_t)(cidx & 1) * 16384u;
        compute_chunk(stA, stA + 8192, stB, stB + 8192, aoff, boff, c);
        __syncthreads();
    }

    // epilogue
    float* sf = (float*)smem;
#pragma unroll
    for (int i = 0; i < 4; i++) {
        const int r = m0 + i * 16 + (lane >> 2);
#pragma unroll
        for (int j = 0; j < 4; j++) {
            const int cc = n0 + j * 8 + (lane & 3) * 2;
            sf[r * 136 + cc]           = c[i][j][0];
            sf[r * 136 + cc + 1]       = c[i][j][1];
            sf[(r + 8) * 136 + cc]     = c[i][j][2];
            sf[(r + 8) * 136 + cc + 1] = c[i][j][3];
        }
    }
    __syncthreads();
#pragma unroll 4
    for (int e = tid; e < 128 * 128; e += TG_THREADS) {
        int r, cc;
        if (transOut) { r = e & 127; cc = e >> 7; }   // r fast => coalesced trans store
        else          { r = e >> 7;  cc = e & 127; }
        float v = sf[r * 136 + cc] + bias[colBase + cc];
        long long gi;
        if (transOut) {
            const int grow = rowBase + r;
            gi = (long long)(grow >> 11) * ((long long)DD * SS)
               + (long long)(colBase + cc) * SS + (grow & 2047);
        } else {
            gi = (long long)(rowBase + r) * N + colBase + cc;
        }
        bf16 h = __float2bfloat16_rn(v);
        outHi[gi] = h;
        outLo[gi] = __float2bfloat16_rn(v - __bfloat162float(h));
    }
}

// ---------------------------------------------------------------------------
// fp32 SGEMM (small 512^3 fold GEMMs only): C = A @ B
// ---------------------------------------------------------------------------
__global__ __launch_bounds__(256)
void sgemm_nn_kernel(const float* __restrict__ A, const float* __restrict__ Bm,
                     float* __restrict__ C, int M, int N, int K)
{
    const int BK = 8;
    __shared__ float As[BK][128];
    __shared__ float Bs[BK][128];
    const int tid = threadIdx.x;
    const int tx = tid & 15, ty = tid >> 4;
    const int rowBase = blockIdx.y * 128, colBase = blockIdx.x * 128;
    float acc[8][8];
#pragma unroll
    for (int i = 0; i < 8; i++)
#pragma unroll
        for (int j = 0; j < 8; j++) acc[i][j] = 0.0f;

    for (int k0 = 0; k0 < K; k0 += BK) {
        {
            const int r = tid >> 1, kc = (tid & 1) * 4;
            float4 a = *reinterpret_cast<const float4*>(A + (long long)(rowBase + r) * K + k0 + kc);
            As[kc + 0][r] = a.x; As[kc + 1][r] = a.y; As[kc + 2][r] = a.z; As[kc + 3][r] = a.w;
        }
        {
            const int kr = tid >> 5, ccc = (tid & 31) * 4;
            float4 b = *reinterpret_cast<const float4*>(Bm + (long long)(k0 + kr) * N + colBase + ccc);
            Bs[kr][ccc + 0] = b.x; Bs[kr][ccc + 1] = b.y; Bs[kr][ccc + 2] = b.z; Bs[kr][ccc + 3] = b.w;
        }
        __syncthreads();
#pragma unroll
        for (int k = 0; k < BK; k++) {
            float4 a0 = *reinterpret_cast<const float4*>(&As[k][ty * 8]);
            float4 a1 = *reinterpret_cast<const float4*>(&As[k][ty * 8 + 4]);
            float4 b0 = *reinterpret_cast<const float4*>(&Bs[k][tx * 8]);
            float4 b1 = *reinterpret_cast<const float4*>(&Bs[k][tx * 8 + 4]);
            float arr[8] = {a0.x, a0.y, a0.z, a0.w, a1.x, a1.y, a1.z, a1.w};
            float brr[8] = {b0.x, b0.y, b0.z, b0.w, b1.x, b1.y, b1.z, b1.w};
#pragma unroll
            for (int i = 0; i < 8; i++)
#pragma unroll
                for (int j = 0; j < 8; j++) acc[i][j] = fmaf(arr[i], brr[j], acc[i][j]);
        }
        __syncthreads();
    }
#pragma unroll
    for (int i = 0; i < 8; i++) {
        const int r = rowBase + ty * 8 + i;
#pragma unroll
        for (int j = 0; j < 8; j += 4) {
            const int cc = colBase + tx * 8 + j;
            float4 v = {acc[i][j], acc[i][j + 1], acc[i][j + 2], acc[i][j + 3]};
            *reinterpret_cast<float4*>(C + (long long)r * N + cc) = v;
        }
    }
}

__global__ void fuse_bias_kernel(const float* __restrict__ E,
                                 const float* __restrict__ b,
                                 float* __restrict__ out)
{
    __shared__ float red[8];
    const int p = blockIdx.x;
    float s = 0.0f;
    for (int d = threadIdx.x; d < DD; d += 256)
        s = fmaf(E[(long long)p * DD + d], b[d], s);
#pragma unroll
    for (int o = 16; o > 0; o >>= 1) s += __shfl_xor_sync(0xffffffffu, s, o);
    if ((threadIdx.x & 31) == 0) red[threadIdx.x >> 5] = s;
    __syncthreads();
    if (threadIdx.x == 0) {
        float t = 0.0f;
#pragma unroll
        for (int i = 0; i < 8; i++) t += red[i];
        out[p] = t;
    }
}

__global__ void split_kernel(const float* __restrict__ x,
                             bf16* __restrict__ hi, bf16* __restrict__ lo,
                             long long n)
{
    long long i = (long long)blockIdx.x * blockDim.x + threadIdx.x;
    const long long stride = (long long)gridDim.x * blockDim.x;
    for (; i < n; i += stride) {
        float v = x[i];
        bf16 h = __float2bfloat16_rn(v);
        hi[i] = h;
        lo[i] = __float2bfloat16_rn(v - __bfloat162float(h));
    }
}

__global__ __launch_bounds__(256)
void softmax2048_kernel(float* __restrict__ data,
                        bf16* __restrict__ ohi, bf16* __restrict__ olo)
{
    const size_t base = (size_t)blockIdx.x * 2048;
    float* row = data + base;
    const int tid = threadIdx.x;
    __shared__ float red[8];

    float v[8];
    float m = -3.4e38f;
#pragma unroll
    for (int i = 0; i < 8; i++) { v[i] = row[tid + 256 * i]; m = fmaxf(m, v[i]); }
#pragma unroll
    for (int o = 16; o > 0; o >>= 1) m = fmaxf(m, __shfl_xor_sync(0xffffffffu, m, o));
    if ((tid & 31) == 0) red[tid >> 5] = m;
    __syncthreads();
    float bm = red[0];
#pragma unroll
    for (int i = 1; i < 8; i++) bm = fmaxf(bm, red[i]);
    __syncthreads();

    float s = 0.0f;
#pragma unroll
    for (int i = 0; i < 8; i++) { v[i] = __expf(v[i] - bm); s += v[i]; }
#pragma unroll
    for (int o = 16; o > 0; o >>= 1) s += __shfl_xor_sync(0xffffffffu, s, o);
    if ((tid & 31) == 0) red[tid >> 5] = s;
    __syncthreads();
    float bs = 0.0f;
#pragma unroll
    for (int i = 0; i < 8; i++) bs += red[i];

    const float inv = 1.0f / bs;
#pragma unroll
    for (int i = 0; i < 8; i++) {
        float r = v[i] * inv;
        const size_t idx = base + tid + 256 * i;
        data[idx] = r;
        bf16 h = __float2bfloat16_rn(r);
        ohi[idx] = h;
        olo[idx] = __float2bfloat16_rn(r - __bfloat162float(h));
    }
}

// ---------------------------------------------------------------------------
// Launch
// ---------------------------------------------------------------------------
extern "C" void kernel_launch(void* const* d_in, const int* in_sizes, int n_in,
                              void* d_out, int out_size)
{
    const float* q_in = (const float*)d_in[0];
    const float* k_in = (const float*)d_in[1];
    const float* v_in = (const float*)d_in[2];
    const float* Wq   = (const float*)d_in[3];
    const float* bq   = (const float*)d_in[4];
    const float* Wk   = (const float*)d_in[5];
    const float* bk   = (const float*)d_in[6];
    const float* Wv   = (const float*)d_in[7];
    const float* bv   = (const float*)d_in[8];
    const float* E1   = (const float*)d_in[9];
    const float* E2   = (const float*)d_in[10];
    const float* Wo   = (const float*)d_in[11];
    const float* bo   = (const float*)d_in[12];

    float* outp = (float*)d_out;
    float* attn = outp + (size_t)BB * SS * DD;

    float *p_Wkp, *p_Wvp, *p_bkp, *p_bvp;
    cudaGetSymbolAddress((void**)&p_Wkp, g_Wkp);
    cudaGetSymbolAddress((void**)&p_Wvp, g_Wvp);
    cudaGetSymbolAddress((void**)&p_bkp, g_bkp);
    cudaGetSymbolAddress((void**)&p_bvp, g_bvp);
    bf16 *wq_h, *wq_l, *wkp_h, *wkp_l, *wvp_h, *wvp_l, *wo_h, *wo_l;
    bf16 *q_h, *q_l, *kp_h, *kp_l, *vpT_h, *vpT_l, *at_h, *at_l, *op_h, *op_l;
    cudaGetSymbolAddress((void**)&wq_h,  g_Wq_hi);  cudaGetSymbolAddress((void**)&wq_l,  g_Wq_lo);
    cudaGetSymbolAddress((void**)&wkp_h, g_Wkp_hi); cudaGetSymbolAddress((void**)&wkp_l, g_Wkp_lo);
    cudaGetSymbolAddress((void**)&wvp_h, g_Wvp_hi); cudaGetSymbolAddress((void**)&wvp_l, g_Wvp_lo);
    cudaGetSymbolAddress((void**)&wo_h,  g_Wo_hi);  cudaGetSymbolAddress((void**)&wo_l,  g_Wo_lo);
    cudaGetSymbolAddress((void**)&q_h,   g_q_hi);   cudaGetSymbolAddress((void**)&q_l,   g_q_lo);
    cudaGetSymbolAddress((void**)&kp_h,  g_kp_hi);  cudaGetSymbolAddress((void**)&kp_l,  g_kp_lo);
    cudaGetSymbolAddress((void**)&vpT_h, g_vpT_hi); cudaGetSymbolAddress((void**)&vpT_l, g_vpT_lo);
    cudaGetSymbolAddress((void**)&at_h,  g_attn_hi);cudaGetSymbolAddress((void**)&at_l,  g_attn_lo);
    cudaGetSymbolAddress((void**)&op_h,  g_op_hi);  cudaGetSymbolAddress((void**)&op_l,  g_op_lo);

    cudaFuncSetAttribute(tgemm_kernel, cudaFuncAttributeMaxDynamicSharedMemorySize, TG_SMEM);
    cudaFuncSetAttribute(tgemm_f32a_kernel, cudaFuncAttributeMaxDynamicSharedMemorySize, TG_SMEM);

    const int M = BB * SS;
    const float scaling = 1.0f / sqrtf((float)DD);
    const dim3 gProj(DD / 128, M / 128, 1);
    const dim3 gFold(DD / 128, DD / 128, 1);

    // ordered so launches 3..5 include tgemm kernels (ncu capture lands there)
    sgemm_nn_kernel<<<gFold, 256>>>(E1, Wk, p_Wkp, DD, DD, DD);             // 0
    split_kernel<<<256, 256>>>(Wq, wq_h, wq_l, (long long)DD * DD);         // 1
    fuse_bias_kernel<<<DD, 256>>>(E1, bk, p_bkp);                           // 2
    tgemm_f32a_kernel<<<gProj, TG_THREADS, TG_SMEM>>>(                      // 3
        q_in, wq_h, wq_l, q_h, q_l, bq, M, DD, DD, 0);
    split_kernel<<<256, 256>>>(p_Wkp, wkp_h, wkp_l, (long long)DD * DD);    // 4
    tgemm_f32a_kernel<<<gProj, TG_THREADS, TG_SMEM>>>(                      // 5
        k_in, wkp_h, wkp_l, kp_h, kp_l, p_bkp, M, DD, DD, 0);
    sgemm_nn_kernel<<<gFold, 256>>>(E2, Wv, p_Wvp, DD, DD, DD);             // 6
    fuse_bias_kernel<<<DD, 256>>>(E2, bv, p_bvp);                           // 7
    split_kernel<<<256, 256>>>(p_Wvp, wvp_h, wvp_l, (long long)DD * DD);    // 8
    tgemm_f32a_kernel<<<gProj, TG_THREADS, TG_SMEM>>>(                      // 9 (vpT direct)
        v_in, wvp_h, wvp_l, vpT_h, vpT_l, p_bvp, M, DD, DD, 1);

    // scores = scaling * q @ kp^T -> attn region fp32
    tgemm_kernel<<<dim3(SS / 128, SS / 128, BB), TG_THREADS, TG_SMEM>>>(
        q_h, q_l, kp_h, kp_l, attn, nullptr, nullptr, nullptr,
        SS, SS, DD, scaling,
        (long long)SS * DD, (long long)SS * DD, (long long)SS * SS);

    softmax2048_kernel<<<BB * SS, 256>>>(attn, at_h, at_l);

    split_kernel<<<256, 256>>>(Wo, wo_h, wo_l, (long long)DD * DD);

    // op = attn @ vpT^T (K = 2048)
    tgemm_kernel<<<dim3(DD / 128, SS / 128, BB), TG_THREADS, TG_SMEM>>>(
        at_h, at_l, vpT_h, vpT_l, nullptr, op_h, op_l, nullptr,
        SS, DD, SS, 1.0f,
        (long long)SS * SS, (long long)SS * DD, (long long)SS * DD);

    // out = op @ Wo^T + bo
    tgemm_kernel<<<dim3(DD / 128, M / 128, 1), TG_THREADS, TG_SMEM>>>(
        op_h, op_l, wo_h, wo_l, outp, nullptr, nullptr, bo,
        M, DD, DD, 1.0f, 0, 0, 0);
}

// round 5
// speedup vs baseline: 1.0396x; 1.0396x over previous
#include <cuda_runtime.h>
#include <cuda_bf16.h>
#include <math.h>
#include <stdint.h>

#define BB 16
#define SS 2048
#define DD 512
typedef __nv_bfloat16 bf16;

// ---------------------------------------------------------------------------
// Scratch (device globals — no allocation allowed)
// ---------------------------------------------------------------------------
__device__ float g_Wkp[DD * DD];
__device__ float g_Wvp[DD * DD];
__device__ float g_bkp[DD];
__device__ float g_bvp[DD];

__device__ bf16 g_Wq_hi[DD * DD],  g_Wq_lo[DD * DD];
__device__ bf16 g_Wkp_hi[DD * DD], g_Wkp_lo[DD * DD];
__device__ bf16 g_Wvp_hi[DD * DD], g_Wvp_lo[DD * DD];
__device__ bf16 g_Wo_hi[DD * DD],  g_Wo_lo[DD * DD];
__device__ bf16 g_q_hi[(size_t)BB * SS * DD],  g_q_lo[(size_t)BB * SS * DD];
__device__ bf16 g_kp_hi[(size_t)BB * SS * DD], g_kp_lo[(size_t)BB * SS * DD];
__device__ bf16 g_vpT_hi[(size_t)BB * SS * DD], g_vpT_lo[(size_t)BB * SS * DD];
__device__ bf16 g_attn_hi[(size_t)BB * SS * SS], g_attn_lo[(size_t)BB * SS * SS];
__device__ bf16 g_op_hi[(size_t)BB * SS * DD],  g_op_lo[(size_t)BB * SS * DD];

// ---------------------------------------------------------------------------
// helpers (portable sm_80+ feature set only: cp.async / ldmatrix / mma.sync)
// ---------------------------------------------------------------------------
__device__ __forceinline__ uint32_t smem_u32(const void* p) {
    uint32_t a;
    asm("{ .reg .u64 t; cvta.to.shared.u64 t, %1; cvt.u32.u64 %0, t; }"
        : "=r"(a) : "l"(p));
    return a;
}
__device__ __forceinline__ void cp_async16(uint32_t dst, const void* src) {
    asm volatile("cp.async.cg.shared.global [%0], [%1], 16;"
                 :: "r"(dst), "l"(src) : "memory");
}
__device__ __forceinline__ void cp_commit() {
    asm volatile("cp.async.commit_group;" ::: "memory");
}
__device__ __forceinline__ void cp_wait1() {
    asm volatile("cp.async.wait_group 1;" ::: "memory");
}
__device__ __forceinline__ void cp_wait0() {
    asm volatile("cp.async.wait_group 0;" ::: "memory");
}
__device__ __forceinline__ void ldsm4(uint32_t r[4], uint32_t addr) {
    asm volatile("ldmatrix.sync.aligned.m8n8.x4.shared.b16 {%0,%1,%2,%3}, [%4];"
                 : "=r"(r[0]), "=r"(r[1]), "=r"(r[2]), "=r"(r[3]) : "r"(addr));
}
__device__ __forceinline__ void mma16816(float c[4], const uint32_t a[4],
                                         uint32_t b0, uint32_t b1) {
    asm volatile(
        "mma.sync.aligned.m16n8k16.row.col.f32.bf16.bf16.f32 "
        "{%0,%1,%2,%3}, {%4,%5,%6,%7}, {%8,%9}, {%0,%1,%2,%3};"
        : "+f"(c[0]), "+f"(c[1]), "+f"(c[2]), "+f"(c[3])
        : "r"(a[0]), "r"(a[1]), "r"(a[2]), "r"(a[3]), "r"(b0), "r"(b1));
}
// 8 fp32 -> 8 hi bf16 + 8 lo bf16 (packed as uint4 each)
__device__ __forceinline__ void split8(const float4 x, const float4 y,
                                       uint4& hi, uint4& lo) {
    float f[8] = {x.x, x.y, x.z, x.w, y.x, y.y, y.z, y.w};
    uint32_t h[4], l[4];
#pragma unroll
    for (int i = 0; i < 4; i++) {
        __nv_bfloat162 hh = __floats2bfloat162_rn(f[2 * i], f[2 * i + 1]);
        h[i] = *reinterpret_cast<uint32_t*>(&hh);
        float r0 = f[2 * i]     - __bfloat162float(hh.x);
        float r1 = f[2 * i + 1] - __bfloat162float(hh.y);
        __nv_bfloat162 ll = __floats2bfloat162_rn(r0, r1);
        l[i] = *reinterpret_cast<uint32_t*>(&ll);
    }
    hi = make_uint4(h[0], h[1], h[2], h[3]);
    lo = make_uint4(l[0], l[1], l[2], l[3]);
}

// shared compute body: 32-K chunk, 3 passes (AhBh, AhBl, AlBh)
__device__ __forceinline__ void compute_chunk(
    uint32_t ah, uint32_t al, uint32_t bhb, uint32_t blb,
    const uint32_t aoff[4][2], const uint32_t boff[2][2], float c[4][4][4])
{
#pragma unroll
    for (int ks = 0; ks < 2; ks++) {
        uint32_t a[4][4], bh[2][4], bl[2][4];
#pragma unroll
        for (int i = 0; i < 4; i++) ldsm4(a[i], ah + aoff[i][ks]);
#pragma unroll
        for (int j = 0; j < 2; j++) ldsm4(bh[j], bhb + boff[j][ks]);
#pragma unroll
        for (int j = 0; j < 2; j++) ldsm4(bl[j], blb + boff[j][ks]);
#pragma unroll
        for (int i = 0; i < 4; i++)
#pragma unroll
            for (int j = 0; j < 4; j++) {
                mma16816(c[i][j], a[i], bh[j >> 1][(j & 1) * 2], bh[j >> 1][(j & 1) * 2 + 1]);
                mma16816(c[i][j], a[i], bl[j >> 1][(j & 1) * 2], bl[j >> 1][(j & 1) * 2 + 1]);
            }
#pragma unroll
        for (int i = 0; i < 4; i++) ldsm4(a[i], al + aoff[i][ks]);
#pragma unroll
        for (int i = 0; i < 4; i++)
#pragma unroll
            for (int j = 0; j < 4; j++)
                mma16816(c[i][j], a[i], bh[j >> 1][(j & 1) * 2], bh[j >> 1][(j & 1) * 2 + 1]);
    }
}

#define TG_THREADS 256
#define TG_STAGE   32768
#define TG_SMEM    (128 * 136 * 4)     // 69632 (also covers 2x32KB stages)

// ---------------------------------------------------------------------------
// Pair-input GEMM (A,B hi/lo bf16): C = alpha*A@B^T (+bias); outputs fp32
// and/or hi/lo pair. __launch_bounds__(256,2): 2 CTAs/SM (128 regs cap).
// ---------------------------------------------------------------------------
__global__ __launch_bounds__(TG_THREADS, 2)
void tgemm_kernel(const bf16* __restrict__ Ahi, const bf16* __restrict__ Alo,
                  const bf16* __restrict__ Bhi, const bf16* __restrict__ Blo,
                  float* outF, bf16* outHi, bf16* outLo,
                  const float* __restrict__ bias,
                  int M, int N, int K, float alpha,
                  long long sA, long long sB, long long sC)
{
    extern __shared__ char smem[];
    const uint32_t sb = smem_u32(smem);
    const int tid  = threadIdx.x;
    const int lane = tid & 31;
    const int wid  = tid >> 5;
    const int m0   = (wid & 1) * 64;
    const int n0   = (wid >> 1) * 32;

    const long long bz = blockIdx.z;
    Ahi += bz * sA; Alo += bz * sA;
    Bhi += bz * sB; Blo += bz * sB;
    if (outF)  outF  += bz * sC;
    if (outHi) { outHi += bz * sC; outLo += bz * sC; }

    const int rowBase = blockIdx.y * 128;
    const int colBase = blockIdx.x * 128;

    int ldRow[2], ldK16[2];
    uint32_t ldOff[2];
#pragma unroll
    for (int i = 0; i < 2; i++) {
        int chunk = tid + i * 256;
        ldRow[i] = chunk >> 2;
        ldK16[i] = chunk & 3;
        ldOff[i] = (uint32_t)(ldRow[i] * 64 +
                   ((ldK16[i] ^ ((ldRow[i] >> 1) & 3)) * 16));
    }

    uint32_t aoff[4][2], boff[2][2];
#pragma unroll
    for (int i = 0; i < 4; i++)
#pragma unroll
        for (int ks = 0; ks < 2; ks++) {
            int r = m0 + i * 16 + (lane & 7) + ((lane >> 3) & 1) * 8;
            int ch = ks * 2 + (lane >> 4);
            aoff[i][ks] = (uint32_t)(r * 64 + ((ch ^ ((r >> 1) & 3)) * 16));
        }
#pragma unroll
    for (int j = 0; j < 2; j++)
#pragma unroll
        for (int ks = 0; ks < 2; ks++) {
            int r = n0 + j * 16 + (lane & 7) + ((lane >> 4) & 1) * 8;
            int ch = ks * 2 + ((lane >> 3) & 1);
            boff[j][ks] = (uint32_t)(r * 64 + ((ch ^ ((r >> 1) & 3)) * 16));
        }

    float c[4][4][4];
#pragma unroll
    for (int i = 0; i < 4; i++)
#pragma unroll
        for (int j = 0; j < 4; j++)
#pragma unroll
            for (int e = 0; e < 4; e++) c[i][j][e] = 0.0f;

    const int nc = K >> 5;

    auto load_stage = [&](int cidx) {
        const uint32_t dst = sb + (uint32_t)(cidx & 1) * TG_STAGE;
        const long long kb = (long long)cidx * 32;
#pragma unroll
        for (int i = 0; i < 2; i++) {
            const long long ea = (long long)(rowBase + ldRow[i]) * K + kb + ldK16[i] * 8;
            const long long eb = (long long)(colBase + ldRow[i]) * K + kb + ldK16[i] * 8;
            cp_async16(dst +         ldOff[i], Ahi + ea);
            cp_async16(dst +  8192 + ldOff[i], Alo + ea);
            cp_async16(dst + 16384 + ldOff[i], Bhi + eb);
            cp_async16(dst + 24576 + ldOff[i], Blo + eb);
        }
        cp_commit();
    };

    load_stage(0);

    for (int cidx = 0; cidx < nc; cidx++) {
        if (cidx + 1 < nc) { load_stage(cidx + 1); cp_wait1(); }
        else               { cp_wait0(); }
        __syncthreads();
        const uint32_t st = sb + (uint32_t)(cidx & 1) * TG_STAGE;
        compute_chunk(st, st + 8192, st + 16384, st + 24576, aoff, boff, c);
        __syncthreads();
    }

    // epilogue
    float* sf = (float*)smem;
#pragma unroll
    for (int i = 0; i < 4; i++) {
        const int r = m0 + i * 16 + (lane >> 2);
#pragma unroll
        for (int j = 0; j < 4; j++) {
            const int cc = n0 + j * 8 + (lane & 3) * 2;
            sf[r * 136 + cc]           = c[i][j][0];
            sf[r * 136 + cc + 1]       = c[i][j][1];
            sf[(r + 8) * 136 + cc]     = c[i][j][2];
            sf[(r + 8) * 136 + cc + 1] = c[i][j][3];
        }
    }
    __syncthreads();
#pragma unroll 4
    for (int e = tid; e < 128 * 128; e += TG_THREADS) {
        const int r = e >> 7, cc = e & 127;
        float v = sf[r * 136 + cc] * alpha;
        const int gc = colBase + cc;
        if (bias) v += bias[gc];
        const long long gi = (long long)(rowBase + r) * N + gc;
        if (outF) outF[gi] = v;
        if (outHi) {
            bf16 h = __float2bfloat16_rn(v);
            outHi[gi] = h;
            outLo[gi] = __float2bfloat16_rn(v - __bfloat162float(h));
        }
    }
}

// ---------------------------------------------------------------------------
// fp32-A GEMM (projections): A fp32 split in-kernel; B pre-split hi/lo bf16.
// C = A@B^T + bias -> hi/lo pair output, optionally transposed (vpT layout).
// ---------------------------------------------------------------------------
__global__ __launch_bounds__(TG_THREADS, 2)
void tgemm_f32a_kernel(const float* __restrict__ A,
                       const bf16* __restrict__ Bhi, const bf16* __restrict__ Blo,
                       bf16* __restrict__ outHi, bf16* __restrict__ outLo,
                       const float* __restrict__ bias,
                       int M, int N, int K, int transOut)
{
    extern __shared__ char smem[];
    const uint32_t sb = smem_u32(smem);
    const int tid  = threadIdx.x;
    const int lane = tid & 31;
    const int wid  = tid >> 5;
    const int m0   = (wid & 1) * 64;
    const int n0   = (wid >> 1) * 32;

    const int rowBase = blockIdx.y * 128;
    const int colBase = blockIdx.x * 128;

    // A-load geometry: 2 units of (row, 8 floats)
    int aRow[2], aC8[2];
    uint32_t aSw[2];
#pragma unroll
    for (int i = 0; i < 2; i++) {
        int u = tid + i * 256;
        aRow[i] = u >> 2;
        aC8[i]  = u & 3;
        aSw[i]  = (uint32_t)(aRow[i] * 64 + ((aC8[i] ^ ((aRow[i] >> 1) & 3)) * 16));
    }
    // B cp.async geometry
    int ldRow[2], ldK16[2];
    uint32_t ldOff[2];
#pragma unroll
    for (int i = 0; i < 2; i++) {
        int chunk = tid + i * 256;
        ldRow[i] = chunk >> 2;
        ldK16[i] = chunk & 3;
        ldOff[i] = (uint32_t)(ldRow[i] * 64 +
                   ((ldK16[i] ^ ((ldRow[i] >> 1) & 3)) * 16));
    }

    uint32_t aoff[4][2], boff[2][2];
#pragma unroll
    for (int i = 0; i < 4; i++)
#pragma unroll
        for (int ks = 0; ks < 2; ks++) {
            int r = m0 + i * 16 + (lane & 7) + ((lane >> 3) & 1) * 8;
            int ch = ks * 2 + (lane >> 4);
            aoff[i][ks] = (uint32_t)(r * 64 + ((ch ^ ((r >> 1) & 3)) * 16));
        }
#pragma unroll
    for (int j = 0; j < 2; j++)
#pragma unroll
        for (int ks = 0; ks < 2; ks++) {
            int r = n0 + j * 16 + (lane & 7) + ((lane >> 4) & 1) * 8;
            int ch = ks * 2 + ((lane >> 3) & 1);
            boff[j][ks] = (uint32_t)(r * 64 + ((ch ^ ((r >> 1) & 3)) * 16));
        }

    float c[4][4][4];
#pragma unroll
    for (int i = 0; i < 4; i++)
#pragma unroll
        for (int j = 0; j < 4; j++)
#pragma unroll
            for (int e = 0; e < 4; e++) c[i][j][e] = 0.0f;

    const int nc = K >> 5;

    auto issueB = [&](int cidx) {
        const uint32_t dst = sb + 32768u + (uint32_t)(cidx & 1) * 16384u;
        const long long kb = (long long)cidx * 32;
#pragma unroll
        for (int i = 0; i < 2; i++) {
            const long long eb = (long long)(colBase + ldRow[i]) * K + kb + ldK16[i] * 8;
            cp_async16(dst +        ldOff[i], Bhi + eb);
            cp_async16(dst + 8192 + ldOff[i], Blo + eb);
        }
        cp_commit();
    };

    // prologue: A chunk 0 -> regs, B chunk 0 async
    float4 ar[2][2];
#pragma unroll
    for (int i = 0; i < 2; i++) {
        const float* p = A + (long long)(rowBase + aRow[i]) * K + aC8[i] * 8;
        ar[i][0] = *(const float4*)(p);
        ar[i][1] = *(const float4*)(p + 4);
    }
    issueB(0);

    for (int cidx = 0; cidx < nc; cidx++) {
        // STS A(cidx) hi/lo
        {
            char* base = smem + (cidx & 1) * 16384;
#pragma unroll
            for (int i = 0; i < 2; i++) {
                uint4 hi, lo;
                split8(ar[i][0], ar[i][1], hi, lo);
                *(uint4*)(base +        aSw[i]) = hi;
                *(uint4*)(base + 8192 + aSw[i]) = lo;
            }
        }
        if (cidx + 1 < nc) { issueB(cidx + 1); cp_wait1(); }
        else               { cp_wait0(); }
        __syncthreads();
        // prefetch next A chunk into regs
        if (cidx + 1 < nc) {
            const long long kb = (long long)(cidx + 1) * 32;
#pragma unroll
            for (int i = 0; i < 2; i++) {
                const float* p = A + (long long)(rowBase + aRow[i]) * K + kb + aC8[i] * 8;
                ar[i][0] = *(const float4*)(p);
                ar[i][1] = *(const float4*)(p + 4);
            }
        }
        const uint32_t stA = sb + (uint32_t)(cidx & 1) * 16384u;
        const uint32_t stB = sb + 32768u + (uint32_t)(cidx & 1) * 16384u;
        compute_chunk(stA, stA + 8192, stB, stB + 8192, aoff, boff, c);
        __syncthreads();
    }

    // epilogue
    float* sf = (float*)smem;
#pragma unroll
    for (int i = 0; i < 4; i++) {
        const int r = m0 + i * 16 + (lane >> 2);
#pragma unroll
        for (int j = 0; j < 4; j++) {
            const int cc = n0 + j * 8 + (lane & 3) * 2;
            sf[r * 136 + cc]           = c[i][j][0];
            sf[r * 136 + cc + 1]       = c[i][j][1];
            sf[(r + 8) * 136 + cc]     = c[i][j][2];
            sf[(r + 8) * 136 + cc + 1] = c[i][j][3];
        }
    }
    __syncthreads();
#pragma unroll 4
    for (int e = tid; e < 128 * 128; e += TG_THREADS) {
        int r, cc;
        if (transOut) { r = e & 127; cc = e >> 7; }   // r fast => coalesced trans store
        else          { r = e >> 7;  cc = e & 127; }
        float v = sf[r * 136 + cc] + bias[colBase + cc];
        long long gi;
        if (transOut) {
            const int grow = rowBase + r;
            gi = (long long)(grow >> 11) * ((long long)DD * SS)
               + (long long)(colBase + cc) * SS + (grow & 2047);
        } else {
            gi = (long long)(rowBase + r) * N + colBase + cc;
        }
        bf16 h = __float2bfloat16_rn(v);
        outHi[gi] = h;
        outLo[gi] = __float2bfloat16_rn(v - __bfloat162float(h));
    }
}

// ---------------------------------------------------------------------------
// fp32 SGEMM (small 512^3 fold GEMMs only): C = A @ B
// ---------------------------------------------------------------------------
__global__ __launch_bounds__(256)
void sgemm_nn_kernel(const float* __restrict__ A, const float* __restrict__ Bm,
                     float* __restrict__ C, int M, int N, int K)
{
    const int BK = 8;
    __shared__ float As[BK][128];
    __shared__ float Bs[BK][128];
    const int tid = threadIdx.x;
    const int tx = tid & 15, ty = tid >> 4;
    const int rowBase = blockIdx.y * 128, colBase = blockIdx.x * 128;
    float acc[8][8];
#pragma unroll
    for (int i = 0; i < 8; i++)
#pragma unroll
        for (int j = 0; j < 8; j++) acc[i][j] = 0.0f;

    for (int k0 = 0; k0 < K; k0 += BK) {
        {
            const int r = tid >> 1, kc = (tid & 1) * 4;
            float4 a = *reinterpret_cast<const float4*>(A + (long long)(rowBase + r) * K + k0 + kc);
            As[kc + 0][r] = a.x; As[kc + 1][r] = a.y; As[kc + 2][r] = a.z; As[kc + 3][r] = a.w;
        }
        {
            const int kr = tid >> 5, ccc = (tid & 31) * 4;
            float4 b = *reinterpret_cast<const float4*>(Bm + (long long)(k0 + kr) * N + colBase + ccc);
            Bs[kr][ccc + 0] = b.x; Bs[kr][ccc + 1] = b.y; Bs[kr][ccc + 2] = b.z; Bs[kr][ccc + 3] = b.w;
        }
        __syncthreads();
#pragma unroll
        for (int k = 0; k < BK; k++) {
            float4 a0 = *reinterpret_cast<const float4*>(&As[k][ty * 8]);
            float4 a1 = *reinterpret_cast<const float4*>(&As[k][ty * 8 + 4]);
            float4 b0 = *reinterpret_cast<const float4*>(&Bs[k][tx * 8]);
            float4 b1 = *reinterpret_cast<const float4*>(&Bs[k][tx * 8 + 4]);
            float arr[8] = {a0.x, a0.y, a0.z, a0.w, a1.x, a1.y, a1.z, a1.w};
            float brr[8] = {b0.x, b0.y, b0.z, b0.w, b1.x, b1.y, b1.z, b1.w};
#pragma unroll
            for (int i = 0; i < 8; i++)
#pragma unroll
                for (int j = 0; j < 8; j++) acc[i][j] = fmaf(arr[i], brr[j], acc[i][j]);
        }
        __syncthreads();
    }
#pragma unroll
    for (int i = 0; i < 8; i++) {
        const int r = rowBase + ty * 8 + i;
#pragma unroll
        for (int j = 0; j < 8; j += 4) {
            const int cc = colBase + tx * 8 + j;
            float4 v = {acc[i][j], acc[i][j + 1], acc[i][j + 2], acc[i][j + 3]};
            *reinterpret_cast<float4*>(C + (long long)r * N + cc) = v;
        }
    }
}

__global__ void fuse_bias_kernel(const float* __restrict__ E,
                                 const float* __restrict__ b,
                                 float* __restrict__ out)
{
    __shared__ float red[8];
    const int p = blockIdx.x;
    float s = 0.0f;
    for (int d = threadIdx.x; d < DD; d += 256)
        s = fmaf(E[(long long)p * DD + d], b[d], s);
#pragma unroll
    for (int o = 16; o > 0; o >>= 1) s += __shfl_xor_sync(0xffffffffu, s, o);
    if ((threadIdx.x & 31) == 0) red[threadIdx.x >> 5] = s;
    __syncthreads();
    if (threadIdx.x == 0) {
        float t = 0.0f;
#pragma unroll
        for (int i = 0; i < 8; i++) t += red[i];
        out[p] = t;
    }
}

__global__ void split_kernel(const float* __restrict__ x,
                             bf16* __restrict__ hi, bf16* __restrict__ lo,
                             long long n)
{
    long long i = (long long)blockIdx.x * blockDim.x + threadIdx.x;
    const long long stride = (long long)gridDim.x * blockDim.x;
    for (; i < n; i += stride) {
        float v = x[i];
        bf16 h = __float2bfloat16_rn(v);
        hi[i] = h;
        lo[i] = __float2bfloat16_rn(v - __bfloat162float(h));
    }
}

__global__ __launch_bounds__(256)
void softmax2048_kernel(float* __restrict__ data,
                        bf16* __restrict__ ohi, bf16* __restrict__ olo)
{
    const size_t base = (size_t)blockIdx.x * 2048;
    float* row = data + base;
    const int tid = threadIdx.x;
    __shared__ float red[8];

    float v[8];
    float m = -3.4e38f;
#pragma unroll
    for (int i = 0; i < 8; i++) { v[i] = row[tid + 256 * i]; m = fmaxf(m, v[i]); }
#pragma unroll
    for (int o = 16; o > 0; o >>= 1) m = fmaxf(m, __shfl_xor_sync(0xffffffffu, m, o));
    if ((tid & 31) == 0) red[tid >> 5] = m;
    __syncthreads();
    float bm = red[0];
#pragma unroll
    for (int i = 1; i < 8; i++) bm = fmaxf(bm, red[i]);
    __syncthreads();

    float s = 0.0f;
#pragma unroll
    for (int i = 0; i < 8; i++) { v[i] = __expf(v[i] - bm); s += v[i]; }
#pragma unroll
    for (int o = 16; o > 0; o >>= 1) s += __shfl_xor_sync(0xffffffffu, s, o);
    if ((tid & 31) == 0) red[tid >> 5] = s;
    __syncthreads();
    float bs = 0.0f;
#pragma unroll
    for (int i = 0; i < 8; i++) bs += red[i];

    const float inv = 1.0f / bs;
#pragma unroll
    for (int i = 0; i < 8; i++) {
        float r = v[i] * inv;
        const size_t idx = base + tid + 256 * i;
        data[idx] = r;
        bf16 h = __float2bfloat16_rn(r);
        ohi[idx] = h;
        olo[idx] = __float2bfloat16_rn(r - __bfloat162float(h));
    }
}

// ---------------------------------------------------------------------------
// Launch
// ---------------------------------------------------------------------------
extern "C" void kernel_launch(void* const* d_in, const int* in_sizes, int n_in,
                              void* d_out, int out_size)
{
    const float* q_in = (const float*)d_in[0];
    const float* k_in = (const float*)d_in[1];
    const float* v_in = (const float*)d_in[2];
    const float* Wq   = (const float*)d_in[3];
    const float* bq   = (const float*)d_in[4];
    const float* Wk   = (const float*)d_in[5];
    const float* bk   = (const float*)d_in[6];
    const float* Wv   = (const float*)d_in[7];
    const float* bv   = (const float*)d_in[8];
    const float* E1   = (const float*)d_in[9];
    const float* E2   = (const float*)d_in[10];
    const float* Wo   = (const float*)d_in[11];
    const float* bo   = (const float*)d_in[12];

    float* outp = (float*)d_out;
    float* attn = outp + (size_t)BB * SS * DD;

    float *p_Wkp, *p_Wvp, *p_bkp, *p_bvp;
    cudaGetSymbolAddress((void**)&p_Wkp, g_Wkp);
    cudaGetSymbolAddress((void**)&p_Wvp, g_Wvp);
    cudaGetSymbolAddress((void**)&p_bkp, g_bkp);
    cudaGetSymbolAddress((void**)&p_bvp, g_bvp);
    bf16 *wq_h, *wq_l, *wkp_h, *wkp_l, *wvp_h, *wvp_l, *wo_h, *wo_l;
    bf16 *q_h, *q_l, *kp_h, *kp_l, *vpT_h, *vpT_l, *at_h, *at_l, *op_h, *op_l;
    cudaGetSymbolAddress((void**)&wq_h,  g_Wq_hi);  cudaGetSymbolAddress((void**)&wq_l,  g_Wq_lo);
    cudaGetSymbolAddress((void**)&wkp_h, g_Wkp_hi); cudaGetSymbolAddress((void**)&wkp_l, g_Wkp_lo);
    cudaGetSymbolAddress((void**)&wvp_h, g_Wvp_hi); cudaGetSymbolAddress((void**)&wvp_l, g_Wvp_lo);
    cudaGetSymbolAddress((void**)&wo_h,  g_Wo_hi);  cudaGetSymbolAddress((void**)&wo_l,  g_Wo_lo);
    cudaGetSymbolAddress((void**)&q_h,   g_q_hi);   cudaGetSymbolAddress((void**)&q_l,   g_q_lo);
    cudaGetSymbolAddress((void**)&kp_h,  g_kp_hi);  cudaGetSymbolAddress((void**)&kp_l,  g_kp_lo);
    cudaGetSymbolAddress((void**)&vpT_h, g_vpT_hi); cudaGetSymbolAddress((void**)&vpT_l, g_vpT_lo);
    cudaGetSymbolAddress((void**)&at_h,  g_attn_hi);cudaGetSymbolAddress((void**)&at_l,  g_attn_lo);
    cudaGetSymbolAddress((void**)&op_h,  g_op_hi);  cudaGetSymbolAddress((void**)&op_l,  g_op_lo);

    cudaFuncSetAttribute(tgemm_kernel, cudaFuncAttributeMaxDynamicSharedMemorySize, TG_SMEM);
    cudaFuncSetAttribute(tgemm_f32a_kernel, cudaFuncAttributeMaxDynamicSharedMemorySize, TG_SMEM);

    const int M = BB * SS;
    const float scaling = 1.0f / sqrtf((float)DD);
    const dim3 gProj(DD / 128, M / 128, 1);
    const dim3 gFold(DD / 128, DD / 128, 1);

    // ordered so launches 3..5 include tgemm kernels (ncu capture lands there)
    sgemm_nn_kernel<<<gFold, 256>>>(E1, Wk, p_Wkp, DD, DD, DD);             // 0
    split_kernel<<<256, 256>>>(Wq, wq_h, wq_l, (long long)DD * DD);         // 1
    fuse_bias_kernel<<<DD, 256>>>(E1, bk, p_bkp);                           // 2
    tgemm_f32a_kernel<<<gProj, TG_THREADS, TG_SMEM>>>(                      // 3
        q_in, wq_h, wq_l, q_h, q_l, bq, M, DD, DD, 0);
    split_kernel<<<256, 256>>>(p_Wkp, wkp_h, wkp_l, (long long)DD * DD);    // 4
    tgemm_f32a_kernel<<<gProj, TG_THREADS, TG_SMEM>>>(                      // 5
        k_in, wkp_h, wkp_l, kp_h, kp_l, p_bkp, M, DD, DD, 0);
    sgemm_nn_kernel<<<gFold, 256>>>(E2, Wv, p_Wvp, DD, DD, DD);             // 6
    fuse_bias_kernel<<<DD, 256>>>(E2, bv, p_bvp);                           // 7
    split_kernel<<<256, 256>>>(p_Wvp, wvp_h, wvp_l, (long long)DD * DD);    // 8
    tgemm_f32a_kernel<<<gProj, TG_THREADS, TG_SMEM>>>(                      // 9 (vpT direct)
        v_in, wvp_h, wvp_l, vpT_h, vpT_l, p_bvp, M, DD, DD, 1);

    // scores = scaling * q @ kp^T -> attn region fp32
    tgemm_kernel<<<dim3(SS / 128, SS / 128, BB), TG_THREADS, TG_SMEM>>>(
        q_h, q_l, kp_h, kp_l, attn, nullptr, nullptr, nullptr,
        SS, SS, DD, scaling,
        (long long)SS * DD, (long long)SS * DD, (long long)SS * SS);

    softmax2048_kernel<<<BB * SS, 256>>>(attn, at_h, at_l);

    split_kernel<<<256, 256>>>(Wo, wo_h, wo_l, (long long)DD * DD);

    // op = attn @ vpT^T (K = 2048)
    tgemm_kernel<<<dim3(DD / 128, SS / 128, BB), TG_THREADS, TG_SMEM>>>(
        at_h, at_l, vpT_h, vpT_l, nullptr, op_h, op_l, nullptr,
        SS, DD, SS, 1.0f,
        (long long)SS * SS, (long long)SS * DD, (long long)SS * DD);

    // out = op @ Wo^T + bo
    tgemm_kernel<<<dim3(DD / 128, M / 128, 1), TG_THREADS, TG_SMEM>>>(
        op_h, op_l, wo_h, wo_l, outp, nullptr, nullptr, bo,
        M, DD, DD, 1.0f, 0, 0, 0);
}